// round 1
// baseline (speedup 1.0000x reference)
#include <cuda_runtime.h>
#include <math.h>

#define DIM   4096
#define NH    32
#define HD    128
#define SEQ   4096
#define BATCH 16

// Scratch (allocation-free): 4 x 256 KB = 1 MB
__device__ float g_q  [BATCH * DIM];
__device__ float g_kn [BATCH * DIM];
__device__ float g_vn [BATCH * DIM];
__device__ float g_att[BATCH * DIM];

// ---------------------------------------------------------------------------
// Skinny GEMM: out[b][j] = dot(x[b,:], W[j,:])  (i.e. x @ W^T), M=16, K=4096.
// One block per output column j (one W row). Weight row streamed once from
// HBM as float4; x (256 KB total) stays L2-resident and is re-read.
// ---------------------------------------------------------------------------
__device__ __forceinline__ void gemm16_row(const float* __restrict__ x,
                                           const float* __restrict__ Wrow,
                                           float* __restrict__ out, int j) {
    const float4* Wr = reinterpret_cast<const float4*>(Wrow);
    const float4* X  = reinterpret_cast<const float4*>(x);

    float acc[BATCH];
#pragma unroll
    for (int b = 0; b < BATCH; b++) acc[b] = 0.f;

    for (int k = threadIdx.x; k < DIM / 4; k += blockDim.x) {
        float4 w = Wr[k];
#pragma unroll
        for (int b = 0; b < BATCH; b++) {
            float4 xv = X[b * (DIM / 4) + k];
            acc[b] += w.x * xv.x + w.y * xv.y + w.z * xv.z + w.w * xv.w;
        }
    }

    // warp butterfly reduce each of the 16 accumulators
#pragma unroll
    for (int b = 0; b < BATCH; b++) {
        float v = acc[b];
        v += __shfl_xor_sync(0xffffffffu, v, 16);
        v += __shfl_xor_sync(0xffffffffu, v, 8);
        v += __shfl_xor_sync(0xffffffffu, v, 4);
        v += __shfl_xor_sync(0xffffffffu, v, 2);
        v += __shfl_xor_sync(0xffffffffu, v, 1);
        acc[b] = v;
    }

    __shared__ float sred[4][BATCH];   // blockDim = 128 -> 4 warps
    int wid  = threadIdx.x >> 5;
    int lane = threadIdx.x & 31;
    if (lane == 0) {
#pragma unroll
        for (int b = 0; b < BATCH; b++) sred[wid][b] = acc[b];
    }
    __syncthreads();
    if (threadIdx.x < BATCH) {
        int b = threadIdx.x;
        float s = sred[0][b] + sred[1][b] + sred[2][b] + sred[3][b];
        out[b * DIM + j] = s;
    }
}

// QKV: grid = 3*4096 blocks. Row r selects wq/wk/wv and the matching scratch.
__global__ void qkv_gemm(const float* __restrict__ x,
                         const float* __restrict__ wq,
                         const float* __restrict__ wk,
                         const float* __restrict__ wv) {
    int r     = blockIdx.x;
    int which = r >> 12;        // r / 4096
    int j     = r & (DIM - 1);  // r % 4096
    const float* W   = (which == 0) ? wq : (which == 1) ? wk : wv;
    float*       out = (which == 0) ? g_q : (which == 1) ? g_kn : g_vn;
    gemm16_row(x, W + (size_t)j * DIM, out, j);
}

// O projection: reads g_att, writes the real output buffer.
__global__ void oproj_gemm(const float* __restrict__ wo,
                           float* __restrict__ out) {
    int j = blockIdx.x;
    gemm16_row(g_att, wo + (size_t)j * DIM, out, j);
}

// ---------------------------------------------------------------------------
// Decode attention. One block per (b,h): 512 blocks, 256 threads = 8 warps.
// Warp w processes key rows w, w+8, ... (4097 rows incl. the new token).
// Each row: coalesced float4 K load, butterfly-reduced dot with q, online
// softmax, coalesced float4 V accumulate. 8-way flash merge in smem.
// ---------------------------------------------------------------------------
__global__ void decode_attn(const float* __restrict__ kc,
                            const float* __restrict__ vc) {
    int bh   = blockIdx.x;          // b*32 + h
    int b    = bh >> 5;
    int h    = bh & 31;
    int tid  = threadIdx.x;
    int w    = tid >> 5;
    int lane = tid & 31;

    const float4* K  = reinterpret_cast<const float4*>(kc + (size_t)bh * SEQ * HD);
    const float4* V  = reinterpret_cast<const float4*>(vc + (size_t)bh * SEQ * HD);
    const float4* Kn = reinterpret_cast<const float4*>(g_kn + b * DIM + h * HD);
    const float4* Vn = reinterpret_cast<const float4*>(g_vn + b * DIM + h * HD);

    // q: 128 floats = 32 float4, one per lane
    float4 q4 = reinterpret_cast<const float4*>(g_q + b * DIM + h * HD)[lane];
    const float scale = 0.08838834764831845f;  // 1/sqrt(128)

    float  m = -INFINITY;
    float  l = 0.f;
    float4 o = make_float4(0.f, 0.f, 0.f, 0.f);

    for (int r = w; r <= SEQ; r += 8) {
        const float4* krow = (r < SEQ) ? (K + (size_t)r * (HD / 4)) : Kn;
        const float4* vrow = (r < SEQ) ? (V + (size_t)r * (HD / 4)) : Vn;

        float4 kv = krow[lane];
        float4 vv = vrow[lane];

        float s = q4.x * kv.x + q4.y * kv.y + q4.z * kv.z + q4.w * kv.w;
        s += __shfl_xor_sync(0xffffffffu, s, 16);
        s += __shfl_xor_sync(0xffffffffu, s, 8);
        s += __shfl_xor_sync(0xffffffffu, s, 4);
        s += __shfl_xor_sync(0xffffffffu, s, 2);
        s += __shfl_xor_sync(0xffffffffu, s, 1);
        s *= scale;

        float nm = fmaxf(m, s);
        float c  = __expf(m - nm);   // 0 when m == -inf
        float p  = __expf(s - nm);
        l   = l * c + p;
        o.x = o.x * c + p * vv.x;
        o.y = o.y * c + p * vv.y;
        o.z = o.z * c + p * vv.z;
        o.w = o.w * c + p * vv.w;
        m   = nm;
    }

    // merge the 8 warp-partials
    __shared__ float  sm[8];
    __shared__ float  sl[8];
    __shared__ float4 so[8][32];
    so[w][lane] = o;
    if (lane == 0) { sm[w] = m; sl[w] = l; }
    __syncthreads();

    if (tid < HD) {
        int d = tid;
        float gm = sm[0];
#pragma unroll
        for (int i = 1; i < 8; i++) gm = fmaxf(gm, sm[i]);
        const float* sof = reinterpret_cast<const float*>(so);
        float num = 0.f, den = 0.f;
#pragma unroll
        for (int i = 0; i < 8; i++) {
            float f = __expf(sm[i] - gm);
            num += f * sof[i * HD + d];
            den += f * sl[i];
        }
        g_att[b * DIM + h * HD + d] = num / den;
    }
}

// ---------------------------------------------------------------------------
extern "C" void kernel_launch(void* const* d_in, const int* in_sizes, int n_in,
                              void* d_out, int out_size) {
    const float* x  = (const float*)d_in[0];
    const float* kc = (const float*)d_in[1];
    const float* vc = (const float*)d_in[2];
    const float* wq = (const float*)d_in[3];
    const float* wk = (const float*)d_in[4];
    const float* wv = (const float*)d_in[5];
    const float* wo = (const float*)d_in[6];
    float* out = (float*)d_out;

    qkv_gemm  <<<3 * DIM, 128>>>(x, wq, wk, wv);
    decode_attn<<<BATCH * NH, 256>>>(kc, vc);
    oproj_gemm<<<DIM, 128>>>(wo, out);
}